// round 12
// baseline (speedup 1.0000x reference)
#include <cuda_runtime.h>
#include <cuda_fp16.h>
#include <stdint.h>

static constexpr int Dk   = 4096;
static constexpr int Oo   = 4096;
static constexpr int Kmid = 128;
static constexpr int NTOK = 8192;
static constexpr int W1   = 148;     // persistent k1 workers
static constexpr int NU   = 1024;    // units = 128 m-blocks x 8 K-chunks(512)

// Scratch (device globals — no allocation allowed)
__device__ __half g_wlowh[NTOK * Kmid];     // 2 MB   score-weighted low acts (fp16)
__device__ __half g_Awh[136 * Dk];          // 1.1 MB [A(128) ; Wr(8)] fp16
__device__ __half g_Bth[Oo * Kmid];         // 1 MB   Bt[o][h*16+rr] fp16
__device__ float  g_part[2 * W1][64 * 136]; // 10.3MB deterministic k1 partials

// ---------------------------------------------------------------------------
// helpers
// ---------------------------------------------------------------------------
__device__ __forceinline__ void mma16(float* c, uint32_t a0, uint32_t a1,
                                      uint32_t a2, uint32_t a3,
                                      uint32_t b0, uint32_t b1) {
    asm volatile(
        "mma.sync.aligned.m16n8k16.row.col.f32.f16.f16.f32 "
        "{%0,%1,%2,%3}, {%4,%5,%6,%7}, {%8,%9}, {%0,%1,%2,%3};\n"
        : "+f"(c[0]), "+f"(c[1]), "+f"(c[2]), "+f"(c[3])
        : "r"(a0), "r"(a1), "r"(a2), "r"(a3), "r"(b0), "r"(b1));
}
#define LDSM4(R0, R1, R2, R3, ADDR) \
    asm volatile("ldmatrix.sync.aligned.m8n8.x4.shared.b16 {%0,%1,%2,%3}, [%4];" \
        : "=r"(R0), "=r"(R1), "=r"(R2), "=r"(R3) : "r"(ADDR))
#define CP16(dst_u32, src_ptr) \
    asm volatile("cp.async.cg.shared.global [%0], [%1], 16;\n" :: "r"(dst_u32), "l"(src_ptr))
#define CP_COMMIT() asm volatile("cp.async.commit_group;\n" ::: "memory")
#define CP_WAIT(N)  asm volatile("cp.async.wait_group %0;\n" :: "n"(N) : "memory")

// ---------------------------------------------------------------------------
// Kernel 0: convert weights to fp16 scratch (vectorized, 4 elems/thread)
// ---------------------------------------------------------------------------
__global__ void prep(const float* __restrict__ A, const float* __restrict__ Wr,
                     const float* __restrict__ Bm) {
    int t = (blockIdx.x * 256 + threadIdx.x) * 4;
    if (t < 136 * Dk) {
        int row = t >> 12, col = t & (Dk - 1);
        const float* src = (row < 128) ? (A + (size_t)row * Dk + col)
                                       : (Wr + (size_t)(row - 128) * Dk + col);
        float4 v = *reinterpret_cast<const float4*>(src);
        uint2 u;
        __half2 h01 = __floats2half2_rn(v.x, v.y);
        __half2 h23 = __floats2half2_rn(v.z, v.w);
        u.x = *reinterpret_cast<uint32_t*>(&h01);
        u.y = *reinterpret_cast<uint32_t*>(&h23);
        *reinterpret_cast<uint2*>(g_Awh + t) = u;
    }
    if (t < Oo * Kmid) {
        int o = t >> 7, k = t & 127;
        int h = k >> 4, rr = k & 15;
        float4 v = *reinterpret_cast<const float4*>(
            &Bm[(((size_t)h * Oo + o) << 4) + rr]);
        uint2 u;
        __half2 h01 = __floats2half2_rn(v.x, v.y);
        __half2 h23 = __floats2half2_rn(v.z, v.w);
        u.x = *reinterpret_cast<uint32_t*>(&h01);
        u.y = *reinterpret_cast<uint32_t*>(&h23);
        *reinterpret_cast<uint2*>(g_Bth + t) = u;
    }
}

// ---------------------------------------------------------------------------
// Kernel 1: persistent balanced low-GEMM.  Unit = (mb: 64 tokens, kc: 512 K).
// Worker w owns units [w*NU/W1, (w+1)*NU/W1); subtiles of BK=64 halves stream
// through a 2-stage x / 3-stage weight cp.async pipeline continuous across
// units.  f32 accumulators flushed (plain STG) per m-block segment into
// g_part[2w+seg].  Router logits via FFMA on the idle fma pipe.
// SMEM: xs@0 (2 x 64*144=9216)  ws@18432 (3 x 136*144=19584)  -> 77184
// ---------------------------------------------------------------------------
static constexpr int K1_SMEM = 18432 + 3 * 19584;   // 77184

__global__ __launch_bounds__(256, 1)
void k1_low(const float* __restrict__ x) {
    extern __shared__ char sm[];
    const uint32_t su = (uint32_t)__cvta_generic_to_shared(sm);
    const int tid = threadIdx.x, wid = tid >> 5, lane = tid & 31;
    const int wm = wid & 1;            // row half  (32 rows)
    const int wn = wid >> 1;           // col quarter (32 cols)
    const int r = lane >> 2, cc = lane & 3;
    const int bid = blockIdx.x;

    const int u0 = bid * NU / W1, u1 = (bid + 1) * NU / W1;
    const int S = (u1 - u0) * 8;       // subtiles (BK=64) in range

    // router pair: tok = tid&63, heads h0,h0+1
    const int rtok = tid & 63;
    const int rh0  = (tid >> 6) << 1;

    // ldmatrix per-lane byte offsets (within a stage buffer)
    const int aoff0 = (wm * 32 + (lane & 15)) * 144 + ((lane >> 4) << 4);
    const int aoff1 = aoff0 + 16 * 144;
    const int boff0 = (wn * 32 + (lane & 7) + ((lane >> 4) << 3)) * 144
                      + (((lane >> 3) & 1) << 4);
    const int boff1 = boff0 + 16 * 144;

    float acc[2][4][4] = {};
    float rl0 = 0.0f, rl1 = 0.0f;
    float4 rx[2][4];
    int seg = 0;

    auto subc = [&](int s, int& mb, int& kk) {
        int u = u0 + (s >> 3);
        mb = u >> 3;
        kk = (((u & 7) << 3) + (s & 7)) << 6;
    };
    auto ldgx = [&](int s, int b) {
        int mb, kk; subc(s, mb, kk);
        const float* xp = x + (size_t)mb * 64 * Dk + kk;
#pragma unroll
        for (int p = 0; p < 4; p++) {
            int i = tid + p * 256, row = i >> 4, q = i & 15;
            rx[b][p] = *reinterpret_cast<const float4*>(xp + (size_t)row * Dk + q * 4);
        }
    };
    auto stsx = [&](int b, int st) {
        char* xb = sm + st * 9216;
#pragma unroll
        for (int p = 0; p < 4; p++) {
            int i = tid + p * 256, row = i >> 4, q = i & 15;
            float4 v = rx[b][p];
            __half2 h01 = __floats2half2_rn(v.x, v.y);
            __half2 h23 = __floats2half2_rn(v.z, v.w);
            uint2 u;
            u.x = *reinterpret_cast<uint32_t*>(&h01);
            u.y = *reinterpret_cast<uint32_t*>(&h23);
            *reinterpret_cast<uint2*>(xb + row * 144 + q * 8) = u;
        }
    };
    auto cpws = [&](int s, int st) {
        int mb, kk; subc(s, mb, kk);
        const __half* wp = g_Awh + kk;
        uint32_t wb = su + 18432 + st * 19584;
#pragma unroll
        for (int p = 0; p < 5; p++) {
            int i = tid + p * 256;
            if (i < 1088) {
                int row = i >> 3, q = i & 7;
                CP16(wb + row * 144 + q * 16, wp + (size_t)row * Dk + q * 8);
            }
        }
    };
    auto flush = [&](int mb) {
        float* slot = g_part[2 * bid + seg];
        seg++;
#pragma unroll
        for (int mt = 0; mt < 2; mt++) {
            int tr = wm * 32 + mt * 16 + r;
#pragma unroll
            for (int nt = 0; nt < 4; nt++) {
                int col = wn * 32 + nt * 8 + 2 * cc;
                *reinterpret_cast<float2*>(&slot[tr * 136 + col]) =
                    make_float2(acc[mt][nt][0], acc[mt][nt][1]);
                *reinterpret_cast<float2*>(&slot[(tr + 8) * 136 + col]) =
                    make_float2(acc[mt][nt][2], acc[mt][nt][3]);
                acc[mt][nt][0] = acc[mt][nt][1] = 0.0f;
                acc[mt][nt][2] = acc[mt][nt][3] = 0.0f;
            }
        }
        slot[rtok * 136 + 128 + rh0]     = rl0;
        slot[rtok * 136 + 128 + rh0 + 1] = rl1;
        rl0 = rl1 = 0.0f;
    };

    // prologue
    ldgx(0, 0);
    stsx(0, 0);
    ldgx(1, 1);
    cpws(0, 0); CP_COMMIT();
    cpws(1, 1); CP_COMMIT();

    for (int s = 0; s < S; s++) {
        CP_WAIT(1);            // weight group for subtile s retired
        __syncthreads();       // publishes cp.async + previous stsx; protects reuse

        if (s + 1 < S) stsx((s + 1) & 1, (s + 1) & 1);
        if (s + 2 < S) { cpws(s + 2, (s + 2) % 3); ldgx(s + 2, s & 1); }
        CP_COMMIT();           // always commit to keep group accounting exact

        const uint32_t xb = su + (s & 1) * 9216;
        const uint32_t wb = su + 18432 + (s % 3) * 19584;
#pragma unroll
        for (int ks = 0; ks < 4; ks++) {
            const int kb = ks * 32;
            uint32_t a[2][4];
            LDSM4(a[0][0], a[0][1], a[0][2], a[0][3], xb + aoff0 + kb);
            LDSM4(a[1][0], a[1][1], a[1][2], a[1][3], xb + aoff1 + kb);
#pragma unroll
            for (int p = 0; p < 2; p++) {
                uint32_t b0, b1, b2, b3;
                LDSM4(b0, b1, b2, b3, wb + ((p == 0) ? boff0 : boff1) + kb);
                mma16(acc[0][2 * p],     a[0][0], a[0][1], a[0][2], a[0][3], b0, b1);
                mma16(acc[1][2 * p],     a[1][0], a[1][1], a[1][2], a[1][3], b0, b1);
                mma16(acc[0][2 * p + 1], a[0][0], a[0][1], a[0][2], a[0][3], b2, b3);
                mma16(acc[1][2 * p + 1], a[1][0], a[1][1], a[1][2], a[1][3], b2, b3);
            }
        }
        // router logits on the fma pipe (hidden under HMMA throughput cap)
        {
            const __half2* xr = (const __half2*)(sm + (s & 1) * 9216 + rtok * 144);
            const __half2* w0 = (const __half2*)(sm + 18432 + (s % 3) * 19584
                                                 + (128 + rh0) * 144);
            const __half2* w1 = (const __half2*)((const char*)w0 + 144);
#pragma unroll
            for (int j = 0; j < 32; j++) {
                float2 xf = __half22float2(xr[j]);
                float2 a0 = __half22float2(w0[j]);
                float2 a1 = __half22float2(w1[j]);
                rl0 = fmaf(xf.x, a0.x, fmaf(xf.y, a0.y, rl0));
                rl1 = fmaf(xf.x, a1.x, fmaf(xf.y, a1.y, rl1));
            }
        }
        // flush at m-block boundary or range end
        int mbc, mbn, kkd;
        subc(s, mbc, kkd);
        bool last = (s == S - 1);
        if (!last) subc(s + 1, mbn, kkd);
        if (last || mbn != mbc) flush(mbc);
    }
}

// ---------------------------------------------------------------------------
// Kernel 1b: epilogue — sum deterministic partials, softmax, write wlowh
// grid = 128 blocks (one per m-block), 256 threads
// ---------------------------------------------------------------------------
__global__ __launch_bounds__(256)
void k1_epi(const float* __restrict__ br) {
    __shared__ float buf[64 * 136];    // 34816 B
    __shared__ float ssc[64 * 8];
    const int mb = blockIdx.x, tid = threadIdx.x;

    // contributing slots (static arithmetic; <= 3)
    int slots[3]; int ns = 0;
    for (int w = 0; w < W1; w++) {
        int a0 = w * NU / W1, a1 = (w + 1) * NU / W1;
        int lo = (a0 > 8 * mb) ? a0 : 8 * mb;
        int hi = (a1 < 8 * mb + 8) ? a1 : 8 * mb + 8;
        if (lo < hi && ns < 3)
            slots[ns++] = 2 * w + (((a0 >> 3) == mb) ? 0 : 1);
    }
    for (int e = tid; e < 64 * 136; e += 256) {
        float v = 0.0f;
        for (int q = 0; q < ns; q++) v += g_part[slots[q]][e];
        buf[e] = v;
    }
    __syncthreads();
    if (tid < 64) {   // softmax over 8 heads, fold H*SCALING = 16
        float l[8], m = -1e30f;
#pragma unroll
        for (int h = 0; h < 8; h++) {
            l[h] = buf[tid * 136 + 128 + h] + br[h];
            m = fmaxf(m, l[h]);
        }
        float s = 0.0f;
#pragma unroll
        for (int h = 0; h < 8; h++) { l[h] = __expf(l[h] - m); s += l[h]; }
        float inv = 16.0f / s;
#pragma unroll
        for (int h = 0; h < 8; h++) ssc[tid * 8 + h] = l[h] * inv;
    }
    __syncthreads();
    for (int i = tid; i < 64 * 64; i += 256) {   // 64 tok x 64 half2
        int tok = i >> 6, c2 = i & 63;
        int c = c2 * 2;
        float sc = ssc[tok * 8 + (c >> 4)];
        __half2 h = __floats2half2_rn(buf[tok * 136 + c] * sc,
                                      buf[tok * 136 + c + 1] * sc);
        *reinterpret_cast<__half2*>(
            &g_wlowh[(size_t)(mb * 64 + tok) * Kmid + c]) = h;
    }
}

// ---------------------------------------------------------------------------
// Kernel 2: out = wlow[8192,128] @ Bt[4096,128]^T — persistent, 2 CTAs/SM
// (unchanged from R10 — verified)
// ---------------------------------------------------------------------------
static constexpr int TB2     = 128 * 272;
static constexpr int K2_SMEM = 3 * TB2;             // 104448
static constexpr int NTILES  = (NTOK / 128) * (Oo / 128);   // 2048
static constexpr int GRID2   = 296;

__global__ __launch_bounds__(256, 2)
void k2_up(float* __restrict__ out) {
    extern __shared__ char sm[];
    const uint32_t su = (uint32_t)__cvta_generic_to_shared(sm);
    const int tid = threadIdx.x, wid = tid >> 5, lane = tid & 31;
    const int nw = wid & 1;
    const int mw = wid >> 1;
    const int r = lane >> 2, cc = lane & 3;

    const int aoff0 = (mw * 32 + (lane & 15)) * 272 + ((lane >> 4) << 4);
    const int aoff1 = aoff0 + 16 * 272;
    int boff[4];
#pragma unroll
    for (int p = 0; p < 4; p++)
        boff[p] = (nw * 64 + p * 16 + (lane & 7) + ((lane >> 4) << 3)) * 272
                  + (((lane >> 3) & 1) << 4);

    auto cp_tile = [&](const __half* src, uint32_t dst_off) {
#pragma unroll
        for (int p = 0; p < 8; p++) {
            int i = tid + p * 256;
            int row = i >> 4, q = i & 15;
            CP16(su + dst_off + row * 272 + q * 16,
                 src + (size_t)row * Kmid + q * 8);
        }
    };

    const int t0 = (blockIdx.x * NTILES) / GRID2;
    const int t1 = ((blockIdx.x + 1) * NTILES) / GRID2;
    int buf = 0, curmb = -1;

    for (int t = t0; t < t1; t++) {
        const int mb = t >> 5, nt = t & 31;
        const int m0 = mb * 128, nb = nt * 128;

        if (mb != curmb) {
            if (curmb >= 0) __syncthreads();   // all warps done reading
            cp_tile(g_wlowh + (size_t)m0 * Kmid, 0);
            buf = 0;
            cp_tile(g_Bth + (size_t)nb * Kmid, (uint32_t)TB2);
            CP_COMMIT();
            curmb = mb;
        }
        CP_WAIT(0);
        __syncthreads();

        const bool nextsame = (t + 1 < t1) && (((t + 1) >> 5) == mb);
        if (nextsame) {
            cp_tile(g_Bth + (size_t)((nt + 1) * 128) * Kmid,
                    (uint32_t)(TB2 + (buf ^ 1) * TB2));
            CP_COMMIT();
        }

        float acc[2][8][4] = {};
        const uint32_t ab = su;
        const uint32_t bb = su + TB2 + buf * TB2;
#pragma unroll
        for (int ks = 0; ks < 8; ks++) {
            const int kb = ks * 32;
            uint32_t a[2][4];
            LDSM4(a[0][0], a[0][1], a[0][2], a[0][3], ab + aoff0 + kb);
            LDSM4(a[1][0], a[1][1], a[1][2], a[1][3], ab + aoff1 + kb);
#pragma unroll
            for (int p = 0; p < 4; p++) {
                uint32_t b0, b1, b2, b3;
                LDSM4(b0, b1, b2, b3, bb + boff[p] + kb);
                mma16(acc[0][2 * p],     a[0][0], a[0][1], a[0][2], a[0][3], b0, b1);
                mma16(acc[1][2 * p],     a[1][0], a[1][1], a[1][2], a[1][3], b0, b1);
                mma16(acc[0][2 * p + 1], a[0][0], a[0][1], a[0][2], a[0][3], b2, b3);
                mma16(acc[1][2 * p + 1], a[1][0], a[1][1], a[1][2], a[1][3], b2, b3);
            }
        }

#pragma unroll
        for (int mt = 0; mt < 2; mt++) {
            int row = m0 + mw * 32 + mt * 16 + r;
#pragma unroll
            for (int j = 0; j < 8; j++) {
                int col = nb + nw * 64 + j * 8 + 2 * cc;
                *reinterpret_cast<float2*>(&out[(size_t)row * Oo + col]) =
                    make_float2(acc[mt][j][0], acc[mt][j][1]);
                *reinterpret_cast<float2*>(&out[(size_t)(row + 8) * Oo + col]) =
                    make_float2(acc[mt][j][2], acc[mt][j][3]);
            }
        }
        if (nextsame) buf ^= 1;
    }
}

// ---------------------------------------------------------------------------
extern "C" void kernel_launch(void* const* d_in, const int* in_sizes, int n_in,
                              void* d_out, int out_size) {
    const float* x  = (const float*)d_in[0];
    const float* A  = (const float*)d_in[1];
    const float* Bm = (const float*)d_in[2];
    const float* Wr = (const float*)d_in[3];
    const float* br = (const float*)d_in[4];
    float* out = (float*)d_out;

    cudaFuncSetAttribute(k1_low, cudaFuncAttributeMaxDynamicSharedMemorySize, K1_SMEM);
    cudaFuncSetAttribute(k2_up,  cudaFuncAttributeMaxDynamicSharedMemorySize, K2_SMEM);

    prep<<<136 * Dk / 4 / 256, 256>>>(A, Wr, Bm);        // 544 blocks
    k1_low<<<W1, 256, K1_SMEM>>>(x);
    k1_epi<<<NTOK / 64, 256>>>(br);
    k2_up<<<GRID2, 256, K2_SMEM>>>(out);
}

// round 13
// speedup vs baseline: 1.3104x; 1.3104x over previous
#include <cuda_runtime.h>
#include <cuda_fp16.h>
#include <stdint.h>

static constexpr int Dk   = 4096;
static constexpr int Oo   = 4096;
static constexpr int Kmid = 128;
static constexpr int NTOK = 8192;
static constexpr int NK1  = 64;       // K-tiles in kernel 1 (4096/64)

// Scratch (device globals — no allocation allowed)
__device__ __half g_wlowh[NTOK * Kmid];   // 2 MB   score-weighted low acts (fp16)
__device__ __half g_Awh[136 * Dk];        // 1.1 MB [A(128) ; Wr(8)] fp16
__device__ __half g_Bth[Oo * Kmid];       // 1 MB   Bt[o][h*16+rr] fp16

// ---------------------------------------------------------------------------
// helpers
// ---------------------------------------------------------------------------
__device__ __forceinline__ void mma16(float* c, uint32_t a0, uint32_t a1,
                                      uint32_t a2, uint32_t a3,
                                      uint32_t b0, uint32_t b1) {
    asm volatile(
        "mma.sync.aligned.m16n8k16.row.col.f32.f16.f16.f32 "
        "{%0,%1,%2,%3}, {%4,%5,%6,%7}, {%8,%9}, {%0,%1,%2,%3};\n"
        : "+f"(c[0]), "+f"(c[1]), "+f"(c[2]), "+f"(c[3])
        : "r"(a0), "r"(a1), "r"(a2), "r"(a3), "r"(b0), "r"(b1));
}
#define LDSM4(R0, R1, R2, R3, ADDR) \
    asm volatile("ldmatrix.sync.aligned.m8n8.x4.shared.b16 {%0,%1,%2,%3}, [%4];" \
        : "=r"(R0), "=r"(R1), "=r"(R2), "=r"(R3) : "r"(ADDR))
#define LDSM2(R0, R1, ADDR) \
    asm volatile("ldmatrix.sync.aligned.m8n8.x2.shared.b16 {%0,%1}, [%2];" \
        : "=r"(R0), "=r"(R1) : "r"(ADDR))
#define CP16(dst_u32, src_ptr) \
    asm volatile("cp.async.cg.shared.global [%0], [%1], 16;\n" :: "r"(dst_u32), "l"(src_ptr))
#define CP_COMMIT() asm volatile("cp.async.commit_group;\n" ::: "memory")
#define CP_WAIT(N)  asm volatile("cp.async.wait_group %0;\n" :: "n"(N) : "memory")

// ---------------------------------------------------------------------------
// Kernel 0: convert weights to fp16 scratch (vectorized)
// ---------------------------------------------------------------------------
__global__ void prep(const float* __restrict__ A, const float* __restrict__ Wr,
                     const float* __restrict__ Bm) {
    int t = (blockIdx.x * 256 + threadIdx.x) * 4;
    if (t < 136 * Dk) {
        int row = t >> 12, col = t & (Dk - 1);
        const float* src = (row < 128) ? (A + (size_t)row * Dk + col)
                                       : (Wr + (size_t)(row - 128) * Dk + col);
        float4 v = *reinterpret_cast<const float4*>(src);
        uint2 u;
        __half2 h01 = __floats2half2_rn(v.x, v.y);
        __half2 h23 = __floats2half2_rn(v.z, v.w);
        u.x = *reinterpret_cast<uint32_t*>(&h01);
        u.y = *reinterpret_cast<uint32_t*>(&h23);
        *reinterpret_cast<uint2*>(g_Awh + t) = u;
    }
    if (t < Oo * Kmid) {
        int o = t >> 7, k = t & 127;
        int h = k >> 4, rr = k & 15;
        float4 v = *reinterpret_cast<const float4*>(
            &Bm[(((size_t)h * Oo + o) << 4) + rr]);
        uint2 u;
        __half2 h01 = __floats2half2_rn(v.x, v.y);
        __half2 h23 = __floats2half2_rn(v.z, v.w);
        u.x = *reinterpret_cast<uint32_t*>(&h01);
        u.y = *reinterpret_cast<uint32_t*>(&h23);
        *reinterpret_cast<uint2*>(g_Bth + t) = u;
    }
}

// ---------------------------------------------------------------------------
// Kernel 1: low = x @ [A;Wr]^T  (BM=32, BN=128 + 8 router, BK=64 halves)
// grid 256, 2 CTAs/SM (16 warps/SM).  Warp w owns n-strip [16w,16w+16);
// router n8 tile on warp 0.  fp16 mma + ldmatrix; 3-stage weight ring,
// 2-stage x path.
// SMEM: slog@0(1K) ssc@1K(1K) xs@2048 (2 x 32*144=4608) ws@11264 (3 x 19584)
// ---------------------------------------------------------------------------
static constexpr int K1_SMEM = 11264 + 3 * 19584;   // 70016 (x2 = 140032 < 228K)

__global__ __launch_bounds__(256, 2)
void k1_low(const float* __restrict__ x, const float* __restrict__ br) {
    extern __shared__ char sm[];
    const uint32_t su = (uint32_t)__cvta_generic_to_shared(sm);
    float* slog = (float*)(sm);
    float* ssc  = (float*)(sm + 1024);

    const int tid = threadIdx.x, wid = tid >> 5, lane = tid & 31;
    const int r = lane >> 2, cc = lane & 3;
    const int tok0 = blockIdx.x * 32;

    // ldmatrix per-lane byte offsets (within a stage buffer)
    const int aoff0 = (lane & 15) * 144 + ((lane >> 4) << 4);
    const int aoff1 = aoff0 + 16 * 144;
    const int boff  = (wid * 16 + (lane & 7) + ((lane >> 4) << 3)) * 144
                      + (((lane >> 3) & 1) << 4);
    const int roff  = (128 + (lane & 7)) * 144 + (((lane >> 3) & 1) << 4);

    float acc[2][2][4] = {};     // [m-tile][n-tile]
    float racc[2][4]   = {};     // router (warp 0)
    float4 rx[2][2];

    auto ldgx = [&](int kt, int b) {
        const float* xp = x + (size_t)tok0 * Dk + kt * 64;
#pragma unroll
        for (int p = 0; p < 2; p++) {
            int i = tid + p * 256, row = i >> 4, q = i & 15;
            rx[b][p] = *reinterpret_cast<const float4*>(xp + (size_t)row * Dk + q * 4);
        }
    };
    auto stsx = [&](int b, int st) {
        char* xb = sm + 2048 + st * 4608;
#pragma unroll
        for (int p = 0; p < 2; p++) {
            int i = tid + p * 256, row = i >> 4, q = i & 15;
            float4 v = rx[b][p];
            __half2 h01 = __floats2half2_rn(v.x, v.y);
            __half2 h23 = __floats2half2_rn(v.z, v.w);
            uint2 u;
            u.x = *reinterpret_cast<uint32_t*>(&h01);
            u.y = *reinterpret_cast<uint32_t*>(&h23);
            *reinterpret_cast<uint2*>(xb + row * 144 + q * 8) = u;
        }
    };
    auto cpws = [&](int kt, int st) {
        const __half* wp = g_Awh + kt * 64;
        uint32_t wb = su + 11264 + st * 19584;
#pragma unroll
        for (int p = 0; p < 5; p++) {
            int i = tid + p * 256;
            if (i < 1088) {
                int row = i >> 3, q = i & 7;
                CP16(wb + row * 144 + q * 16, wp + (size_t)row * Dk + q * 8);
            }
        }
    };

    // prologue
    ldgx(0, 0);
    stsx(0, 0);
    ldgx(1, 1);
    cpws(0, 0); CP_COMMIT();
    cpws(1, 1); CP_COMMIT();

    for (int kt = 0; kt < NK1; kt++) {
        CP_WAIT(1);            // weight group for tile kt retired
        __syncthreads();       // publishes cp.async + previous stsx; protects reuse

        if (kt + 1 < NK1) stsx((kt + 1) & 1, (kt + 1) & 1);
        if (kt + 2 < NK1) { cpws(kt + 2, (kt + 2) % 3); ldgx(kt + 2, kt & 1); }
        CP_COMMIT();           // always commit to keep group accounting exact

        const uint32_t xb = su + 2048 + (kt & 1) * 4608;
        const uint32_t wb = su + 11264 + (kt % 3) * 19584;
#pragma unroll
        for (int ks = 0; ks < 4; ks++) {
            const int kb = ks * 32;
            uint32_t a[2][4];
            LDSM4(a[0][0], a[0][1], a[0][2], a[0][3], xb + aoff0 + kb);
            LDSM4(a[1][0], a[1][1], a[1][2], a[1][3], xb + aoff1 + kb);
            uint32_t b0, b1, b2, b3;
            LDSM4(b0, b1, b2, b3, wb + boff + kb);
            mma16(acc[0][0], a[0][0], a[0][1], a[0][2], a[0][3], b0, b1);
            mma16(acc[1][0], a[1][0], a[1][1], a[1][2], a[1][3], b0, b1);
            mma16(acc[0][1], a[0][0], a[0][1], a[0][2], a[0][3], b2, b3);
            mma16(acc[1][1], a[1][0], a[1][1], a[1][2], a[1][3], b2, b3);
            if (wid == 0) {
                uint32_t rb0, rb1;
                LDSM2(rb0, rb1, wb + roff + kb);
                mma16(racc[0], a[0][0], a[0][1], a[0][2], a[0][3], rb0, rb1);
                mma16(racc[1], a[1][0], a[1][1], a[1][2], a[1][3], rb0, rb1);
            }
        }
    }

    // router logits -> slog (warp 0 covers all 32 tokens)
    if (wid == 0) {
#pragma unroll
        for (int mt = 0; mt < 2; mt++) {
            int tr = mt * 16 + r;
            slog[tr * 8 + 2 * cc]           = racc[mt][0];
            slog[tr * 8 + 2 * cc + 1]       = racc[mt][1];
            slog[(tr + 8) * 8 + 2 * cc]     = racc[mt][2];
            slog[(tr + 8) * 8 + 2 * cc + 1] = racc[mt][3];
        }
    }
    __syncthreads();
    if (tid < 32) {   // softmax over 8 heads, fold H*SCALING = 16
        float l[8], m = -1e30f;
#pragma unroll
        for (int h = 0; h < 8; h++) {
            l[h] = slog[tid * 8 + h] + br[h];
            m = fmaxf(m, l[h]);
        }
        float s = 0.0f;
#pragma unroll
        for (int h = 0; h < 8; h++) { l[h] = __expf(l[h] - m); s += l[h]; }
        float inv = 16.0f / s;
#pragma unroll
        for (int h = 0; h < 8; h++) ssc[tid * 8 + h] = l[h] * inv;
    }
    __syncthreads();

    // scale + store wlow (fp16); head = wid (16-col strip per head half)
#pragma unroll
    for (int mt = 0; mt < 2; mt++) {
        int tr = mt * 16 + r;
        float s0 = ssc[tr * 8 + (wid >> 1) * 0 + wid];       // head = wid
        float s1 = ssc[(tr + 8) * 8 + wid];
#pragma unroll
        for (int nt = 0; nt < 2; nt++) {
            int col = wid * 16 + nt * 8 + 2 * cc;
            *reinterpret_cast<__half2*>(&g_wlowh[(size_t)(tok0 + tr) * Kmid + col]) =
                __floats2half2_rn(acc[mt][nt][0] * s0, acc[mt][nt][1] * s0);
            *reinterpret_cast<__half2*>(&g_wlowh[(size_t)(tok0 + tr + 8) * Kmid + col]) =
                __floats2half2_rn(acc[mt][nt][2] * s1, acc[mt][nt][3] * s1);
        }
    }
}

// ---------------------------------------------------------------------------
// Kernel 2: out = wlow[8192,128] @ Bt[4096,128]^T — persistent, 2 CTAs/SM
// (unchanged from R10 — verified)
// ---------------------------------------------------------------------------
static constexpr int TB2     = 128 * 272;
static constexpr int K2_SMEM = 3 * TB2;             // 104448
static constexpr int NTILES  = (NTOK / 128) * (Oo / 128);   // 2048
static constexpr int GRID2   = 296;

__global__ __launch_bounds__(256, 2)
void k2_up(float* __restrict__ out) {
    extern __shared__ char sm[];
    const uint32_t su = (uint32_t)__cvta_generic_to_shared(sm);
    const int tid = threadIdx.x, wid = tid >> 5, lane = tid & 31;
    const int nw = wid & 1;
    const int mw = wid >> 1;
    const int r = lane >> 2, cc = lane & 3;

    const int aoff0 = (mw * 32 + (lane & 15)) * 272 + ((lane >> 4) << 4);
    const int aoff1 = aoff0 + 16 * 272;
    int boff[4];
#pragma unroll
    for (int p = 0; p < 4; p++)
        boff[p] = (nw * 64 + p * 16 + (lane & 7) + ((lane >> 4) << 3)) * 272
                  + (((lane >> 3) & 1) << 4);

    auto cp_tile = [&](const __half* src, uint32_t dst_off) {
#pragma unroll
        for (int p = 0; p < 8; p++) {
            int i = tid + p * 256;
            int row = i >> 4, q = i & 15;
            CP16(su + dst_off + row * 272 + q * 16,
                 src + (size_t)row * Kmid + q * 8);
        }
    };

    const int t0 = (blockIdx.x * NTILES) / GRID2;
    const int t1 = ((blockIdx.x + 1) * NTILES) / GRID2;
    int buf = 0, curmb = -1;

    for (int t = t0; t < t1; t++) {
        const int mb = t >> 5, nt = t & 31;
        const int m0 = mb * 128, nb = nt * 128;

        if (mb != curmb) {
            if (curmb >= 0) __syncthreads();   // all warps done reading
            cp_tile(g_wlowh + (size_t)m0 * Kmid, 0);
            buf = 0;
            cp_tile(g_Bth + (size_t)nb * Kmid, (uint32_t)TB2);
            CP_COMMIT();
            curmb = mb;
        }
        CP_WAIT(0);
        __syncthreads();

        const bool nextsame = (t + 1 < t1) && (((t + 1) >> 5) == mb);
        if (nextsame) {
            cp_tile(g_Bth + (size_t)((nt + 1) * 128) * Kmid,
                    (uint32_t)(TB2 + (buf ^ 1) * TB2));
            CP_COMMIT();
        }

        float acc[2][8][4] = {};
        const uint32_t ab = su;
        const uint32_t bb = su + TB2 + buf * TB2;
#pragma unroll
        for (int ks = 0; ks < 8; ks++) {
            const int kb = ks * 32;
            uint32_t a[2][4];
            LDSM4(a[0][0], a[0][1], a[0][2], a[0][3], ab + aoff0 + kb);
            LDSM4(a[1][0], a[1][1], a[1][2], a[1][3], ab + aoff1 + kb);
#pragma unroll
            for (int p = 0; p < 4; p++) {
                uint32_t b0, b1, b2, b3;
                LDSM4(b0, b1, b2, b3, bb + boff[p] + kb);
                mma16(acc[0][2 * p],     a[0][0], a[0][1], a[0][2], a[0][3], b0, b1);
                mma16(acc[1][2 * p],     a[1][0], a[1][1], a[1][2], a[1][3], b0, b1);
                mma16(acc[0][2 * p + 1], a[0][0], a[0][1], a[0][2], a[0][3], b2, b3);
                mma16(acc[1][2 * p + 1], a[1][0], a[1][1], a[1][2], a[1][3], b2, b3);
            }
        }

#pragma unroll
        for (int mt = 0; mt < 2; mt++) {
            int row = m0 + mw * 32 + mt * 16 + r;
#pragma unroll
            for (int j = 0; j < 8; j++) {
                int col = nb + nw * 64 + j * 8 + 2 * cc;
                *reinterpret_cast<float2*>(&out[(size_t)row * Oo + col]) =
                    make_float2(acc[mt][j][0], acc[mt][j][1]);
                *reinterpret_cast<float2*>(&out[(size_t)(row + 8) * Oo + col]) =
                    make_float2(acc[mt][j][2], acc[mt][j][3]);
            }
        }
        if (nextsame) buf ^= 1;
    }
}

// ---------------------------------------------------------------------------
extern "C" void kernel_launch(void* const* d_in, const int* in_sizes, int n_in,
                              void* d_out, int out_size) {
    const float* x  = (const float*)d_in[0];
    const float* A  = (const float*)d_in[1];
    const float* Bm = (const float*)d_in[2];
    const float* Wr = (const float*)d_in[3];
    const float* br = (const float*)d_in[4];
    float* out = (float*)d_out;

    cudaFuncSetAttribute(k1_low, cudaFuncAttributeMaxDynamicSharedMemorySize, K1_SMEM);
    cudaFuncSetAttribute(k2_up,  cudaFuncAttributeMaxDynamicSharedMemorySize, K2_SMEM);

    prep<<<136 * Dk / 4 / 256, 256>>>(A, Wr, Bm);
    k1_low<<<NTOK / 32, 256, K1_SMEM>>>(x, br);
    k2_up<<<GRID2, 256, K2_SMEM>>>(out);
}

// round 14
// speedup vs baseline: 1.8182x; 1.3875x over previous
#include <cuda_runtime.h>
#include <cuda_fp16.h>
#include <stdint.h>

static constexpr int Dk   = 4096;
static constexpr int Oo   = 4096;
static constexpr int Kmid = 128;
static constexpr int NTOK = 8192;
static constexpr int KSPL = 4;        // k1 K-split
static constexpr int NK1  = 16;       // K-tiles per k1 CTA (1024/64)

// Scratch (device globals — no allocation allowed)
__device__ __half g_wlowh[NTOK * Kmid];      // 2 MB   score-weighted low acts
__device__ __half g_Awh[136 * Dk];           // 1.1 MB [A(128) ; Wr(8)] fp16
__device__ __half g_Bth[Oo * Kmid];          // 1 MB   Bt[o][h*16+rr] fp16
__device__ float  g_part[256][128 * 136];    // 17.8MB deterministic k1 partials

// ---------------------------------------------------------------------------
// helpers
// ---------------------------------------------------------------------------
__device__ __forceinline__ void mma16(float* c, uint32_t a0, uint32_t a1,
                                      uint32_t a2, uint32_t a3,
                                      uint32_t b0, uint32_t b1) {
    asm volatile(
        "mma.sync.aligned.m16n8k16.row.col.f32.f16.f16.f32 "
        "{%0,%1,%2,%3}, {%4,%5,%6,%7}, {%8,%9}, {%0,%1,%2,%3};\n"
        : "+f"(c[0]), "+f"(c[1]), "+f"(c[2]), "+f"(c[3])
        : "r"(a0), "r"(a1), "r"(a2), "r"(a3), "r"(b0), "r"(b1));
}
#define LDSM4(R0, R1, R2, R3, ADDR) \
    asm volatile("ldmatrix.sync.aligned.m8n8.x4.shared.b16 {%0,%1,%2,%3}, [%4];" \
        : "=r"(R0), "=r"(R1), "=r"(R2), "=r"(R3) : "r"(ADDR))
#define LDSM2(R0, R1, ADDR) \
    asm volatile("ldmatrix.sync.aligned.m8n8.x2.shared.b16 {%0,%1}, [%2];" \
        : "=r"(R0), "=r"(R1) : "r"(ADDR))
#define CP16(dst_u32, src_ptr) \
    asm volatile("cp.async.cg.shared.global [%0], [%1], 16;\n" :: "r"(dst_u32), "l"(src_ptr))
#define CP_COMMIT() asm volatile("cp.async.commit_group;\n" ::: "memory")
#define CP_WAIT(N)  asm volatile("cp.async.wait_group %0;\n" :: "n"(N) : "memory")

// ---------------------------------------------------------------------------
// Kernel 0: convert weights to fp16 scratch (vectorized)
// ---------------------------------------------------------------------------
__global__ void prep(const float* __restrict__ A, const float* __restrict__ Wr,
                     const float* __restrict__ Bm) {
    int t = (blockIdx.x * 256 + threadIdx.x) * 4;
    if (t < 136 * Dk) {
        int row = t >> 12, col = t & (Dk - 1);
        const float* src = (row < 128) ? (A + (size_t)row * Dk + col)
                                       : (Wr + (size_t)(row - 128) * Dk + col);
        float4 v = *reinterpret_cast<const float4*>(src);
        uint2 u;
        __half2 h01 = __floats2half2_rn(v.x, v.y);
        __half2 h23 = __floats2half2_rn(v.z, v.w);
        u.x = *reinterpret_cast<uint32_t*>(&h01);
        u.y = *reinterpret_cast<uint32_t*>(&h23);
        *reinterpret_cast<uint2*>(g_Awh + t) = u;
    }
    if (t < Oo * Kmid) {
        int o = t >> 7, k = t & 127;
        int h = k >> 4, rr = k & 15;
        float4 v = *reinterpret_cast<const float4*>(
            &Bm[(((size_t)h * Oo + o) << 4) + rr]);
        uint2 u;
        __half2 h01 = __floats2half2_rn(v.x, v.y);
        __half2 h23 = __floats2half2_rn(v.z, v.w);
        u.x = *reinterpret_cast<uint32_t*>(&h01);
        u.y = *reinterpret_cast<uint32_t*>(&h23);
        *reinterpret_cast<uint2*>(g_Bth + t) = u;
    }
}

// ---------------------------------------------------------------------------
// Kernel 1: partial low-GEMM.  CTA = (mb: 128 tokens) x (ksplit: 1024 K).
// BM=128, BN=136 (128 low + 8 router), BK=64 halves; warp tile 32x64,
// router n8 on wn==0 warps.  f32 partials -> g_part[bid] (fixed slot).
// SMEM: xs@0 (2 x 128*144=18432) ws@36864 (3 x 136*144=19584) -> 95616
// ---------------------------------------------------------------------------
static constexpr int K1_SMEM = 36864 + 3 * 19584;   // 95616 (x2 = 191232)

__global__ __launch_bounds__(256, 2)
void k1_low(const float* __restrict__ x) {
    extern __shared__ char sm[];
    const uint32_t su = (uint32_t)__cvta_generic_to_shared(sm);
    const int tid = threadIdx.x, wid = tid >> 5, lane = tid & 31;
    const int wn = wid & 1;            // col half  (64)
    const int wm = wid >> 1;           // row quarter (32)
    const int r = lane >> 2, cc = lane & 3;
    const int mb = blockIdx.x >> 2;            // m-block (128 tokens)
    const int kb0 = (blockIdx.x & 3) * 1024;   // K-chunk base

    // ldmatrix per-lane byte offsets (within a stage buffer)
    const int aoff0 = (wm * 32 + (lane & 15)) * 144 + ((lane >> 4) << 4);
    const int aoff1 = aoff0 + 16 * 144;
    int boff[4];
#pragma unroll
    for (int p = 0; p < 4; p++)
        boff[p] = (wn * 64 + p * 16 + (lane & 7) + ((lane >> 4) << 3)) * 144
                  + (((lane >> 3) & 1) << 4);
    const int roff = (128 + (lane & 7)) * 144 + (((lane >> 3) & 1) << 4);

    float acc[2][8][4] = {};
    float racc[2][4]   = {};
    float4 rx[8];                      // single x staging buffer (32 regs)

    auto ldgx = [&](int s) {           // tile s -> rx
        const float* xp = x + (size_t)mb * 128 * Dk + kb0 + s * 64;
#pragma unroll
        for (int p = 0; p < 8; p++) {
            int i = tid + p * 256, row = i >> 4, q = i & 15;
            rx[p] = *reinterpret_cast<const float4*>(xp + (size_t)row * Dk + q * 4);
            // NOTE: rx[p] overwritten each p — must store per-p; see stsx pairing
        }
    };
    (void)ldgx;                        // replaced by fused version below

    auto ldgx8 = [&](int s, float4* dst) {
        const float* xp = x + (size_t)mb * 128 * Dk + kb0 + s * 64;
#pragma unroll
        for (int p = 0; p < 8; p++) {
            int i = tid + p * 256, row = i >> 4, q = i & 15;
            dst[p] = *reinterpret_cast<const float4*>(xp + (size_t)row * Dk + q * 4);
        }
    };
    auto stsx8 = [&](const float4* src, int st) {
        char* xb = sm + st * 18432;
#pragma unroll
        for (int p = 0; p < 8; p++) {
            int i = tid + p * 256, row = i >> 4, q = i & 15;
            float4 v = src[p];
            __half2 h01 = __floats2half2_rn(v.x, v.y);
            __half2 h23 = __floats2half2_rn(v.z, v.w);
            uint2 u;
            u.x = *reinterpret_cast<uint32_t*>(&h01);
            u.y = *reinterpret_cast<uint32_t*>(&h23);
            *reinterpret_cast<uint2*>(xb + row * 144 + q * 8) = u;
        }
    };
    auto cpws = [&](int s, int st) {
        const __half* wp = g_Awh + kb0 + s * 64;
        uint32_t wb = su + 36864 + st * 19584;
#pragma unroll
        for (int p = 0; p < 5; p++) {
            int i = tid + p * 256;
            if (i < 1088) {
                int row = i >> 3, q = i & 7;
                CP16(wb + row * 144 + q * 16, wp + (size_t)row * Dk + q * 8);
            }
        }
    };

    // prologue
    ldgx8(0, rx);
    stsx8(rx, 0);
    ldgx8(1, rx);
    cpws(0, 0); CP_COMMIT();
    cpws(1, 1); CP_COMMIT();

    for (int s = 0; s < NK1; s++) {
        CP_WAIT(1);            // weight group for tile s retired
        __syncthreads();       // publishes cp.async + previous stsx; protects reuse

        if (s + 1 < NK1) stsx8(rx, (s + 1) & 1);          // rx holds tile s+1
        if (s + 2 < NK1) { cpws(s + 2, (s + 2) % 3); ldgx8(s + 2, rx); }
        CP_COMMIT();           // always commit to keep group accounting exact

        const uint32_t xb = su + (s & 1) * 18432;
        const uint32_t wb = su + 36864 + (s % 3) * 19584;
#pragma unroll
        for (int ks = 0; ks < 4; ks++) {
            const int kb = ks * 32;
            uint32_t a[2][4];
            LDSM4(a[0][0], a[0][1], a[0][2], a[0][3], xb + aoff0 + kb);
            LDSM4(a[1][0], a[1][1], a[1][2], a[1][3], xb + aoff1 + kb);
#pragma unroll
            for (int p = 0; p < 4; p++) {
                uint32_t b0, b1, b2, b3;
                LDSM4(b0, b1, b2, b3, wb + boff[p] + kb);
                mma16(acc[0][2 * p],     a[0][0], a[0][1], a[0][2], a[0][3], b0, b1);
                mma16(acc[1][2 * p],     a[1][0], a[1][1], a[1][2], a[1][3], b0, b1);
                mma16(acc[0][2 * p + 1], a[0][0], a[0][1], a[0][2], a[0][3], b2, b3);
                mma16(acc[1][2 * p + 1], a[1][0], a[1][1], a[1][2], a[1][3], b2, b3);
            }
            if (wn == 0) {
                uint32_t rb0, rb1;
                LDSM2(rb0, rb1, wb + roff + kb);
                mma16(racc[0], a[0][0], a[0][1], a[0][2], a[0][3], rb0, rb1);
                mma16(racc[1], a[1][0], a[1][1], a[1][2], a[1][3], rb0, rb1);
            }
        }
    }

    // flush f32 partials (fixed slot = bid; no atomics, deterministic)
    float* slot = g_part[blockIdx.x];
#pragma unroll
    for (int mt = 0; mt < 2; mt++) {
        int tr = wm * 32 + mt * 16 + r;
#pragma unroll
        for (int j = 0; j < 8; j++) {
            int col = wn * 64 + j * 8 + 2 * cc;
            *reinterpret_cast<float2*>(&slot[tr * 136 + col]) =
                make_float2(acc[mt][j][0], acc[mt][j][1]);
            *reinterpret_cast<float2*>(&slot[(tr + 8) * 136 + col]) =
                make_float2(acc[mt][j][2], acc[mt][j][3]);
        }
        if (wn == 0) {
            slot[tr * 136 + 128 + 2 * cc]       = racc[mt][0];
            slot[tr * 136 + 128 + 2 * cc + 1]   = racc[mt][1];
            slot[(tr + 8) * 136 + 128 + 2 * cc]     = racc[mt][2];
            slot[(tr + 8) * 136 + 128 + 2 * cc + 1] = racc[mt][3];
        }
    }
}

// ---------------------------------------------------------------------------
// Kernel 1b: sum 4 fixed slots, softmax, write wlowh.  grid = 64 m-blocks.
// dynamic SMEM: buf[128*136] f32 (69632) + ssc[128*8] (4096) = 73728
// ---------------------------------------------------------------------------
__global__ __launch_bounds__(256)
void k1_epi(const float* __restrict__ br) {
    extern __shared__ char sme[];
    float* buf = (float*)sme;
    float* ssc = (float*)(sme + 69632);
    const int mb = blockIdx.x, tid = threadIdx.x;

    // sum partials (fixed order -> deterministic); float4 vectorized
    {
        const float4* p0 = reinterpret_cast<const float4*>(g_part[4 * mb + 0]);
        const float4* p1 = reinterpret_cast<const float4*>(g_part[4 * mb + 1]);
        const float4* p2 = reinterpret_cast<const float4*>(g_part[4 * mb + 2]);
        const float4* p3 = reinterpret_cast<const float4*>(g_part[4 * mb + 3]);
        float4* bo = reinterpret_cast<float4*>(buf);
        for (int e = tid; e < 128 * 136 / 4; e += 256) {
            float4 a = p0[e], b = p1[e], c = p2[e], d = p3[e];
            bo[e] = make_float4(a.x + b.x + c.x + d.x, a.y + b.y + c.y + d.y,
                                a.z + b.z + c.z + d.z, a.w + b.w + c.w + d.w);
        }
    }
    __syncthreads();
    if (tid < 128) {   // softmax over 8 heads, fold H*SCALING = 16
        float l[8], m = -1e30f;
#pragma unroll
        for (int h = 0; h < 8; h++) {
            l[h] = buf[tid * 136 + 128 + h] + br[h];
            m = fmaxf(m, l[h]);
        }
        float s = 0.0f;
#pragma unroll
        for (int h = 0; h < 8; h++) { l[h] = __expf(l[h] - m); s += l[h]; }
        float inv = 16.0f / s;
#pragma unroll
        for (int h = 0; h < 8; h++) ssc[tid * 8 + h] = l[h] * inv;
    }
    __syncthreads();
    for (int i = tid; i < 128 * 64; i += 256) {   // 128 tok x 64 half2
        int tok = i >> 6, c = (i & 63) * 2;
        float sc = ssc[tok * 8 + (c >> 4)];
        __half2 h = __floats2half2_rn(buf[tok * 136 + c] * sc,
                                      buf[tok * 136 + c + 1] * sc);
        *reinterpret_cast<__half2*>(
            &g_wlowh[(size_t)(mb * 128 + tok) * Kmid + c]) = h;
    }
}

// ---------------------------------------------------------------------------
// Kernel 2: out = wlow[8192,128] @ Bt[4096,128]^T — persistent, 2 CTAs/SM
// (unchanged from R10/R13 — verified)
// ---------------------------------------------------------------------------
static constexpr int TB2     = 128 * 272;
static constexpr int K2_SMEM = 3 * TB2;             // 104448
static constexpr int NTILES  = (NTOK / 128) * (Oo / 128);   // 2048
static constexpr int GRID2   = 296;

__global__ __launch_bounds__(256, 2)
void k2_up(float* __restrict__ out) {
    extern __shared__ char sm[];
    const uint32_t su = (uint32_t)__cvta_generic_to_shared(sm);
    const int tid = threadIdx.x, wid = tid >> 5, lane = tid & 31;
    const int nw = wid & 1;
    const int mw = wid >> 1;
    const int r = lane >> 2, cc = lane & 3;

    const int aoff0 = (mw * 32 + (lane & 15)) * 272 + ((lane >> 4) << 4);
    const int aoff1 = aoff0 + 16 * 272;
    int boff[4];
#pragma unroll
    for (int p = 0; p < 4; p++)
        boff[p] = (nw * 64 + p * 16 + (lane & 7) + ((lane >> 4) << 3)) * 272
                  + (((lane >> 3) & 1) << 4);

    auto cp_tile = [&](const __half* src, uint32_t dst_off) {
#pragma unroll
        for (int p = 0; p < 8; p++) {
            int i = tid + p * 256;
            int row = i >> 4, q = i & 15;
            CP16(su + dst_off + row * 272 + q * 16,
                 src + (size_t)row * Kmid + q * 8);
        }
    };

    const int t0 = (blockIdx.x * NTILES) / GRID2;
    const int t1 = ((blockIdx.x + 1) * NTILES) / GRID2;
    int buf = 0, curmb = -1;

    for (int t = t0; t < t1; t++) {
        const int mb = t >> 5, nt = t & 31;
        const int m0 = mb * 128, nb = nt * 128;

        if (mb != curmb) {
            if (curmb >= 0) __syncthreads();   // all warps done reading
            cp_tile(g_wlowh + (size_t)m0 * Kmid, 0);
            buf = 0;
            cp_tile(g_Bth + (size_t)nb * Kmid, (uint32_t)TB2);
            CP_COMMIT();
            curmb = mb;
        }
        CP_WAIT(0);
        __syncthreads();

        const bool nextsame = (t + 1 < t1) && (((t + 1) >> 5) == mb);
        if (nextsame) {
            cp_tile(g_Bth + (size_t)((nt + 1) * 128) * Kmid,
                    (uint32_t)(TB2 + (buf ^ 1) * TB2));
            CP_COMMIT();
        }

        float acc[2][8][4] = {};
        const uint32_t ab = su;
        const uint32_t bb = su + TB2 + buf * TB2;
#pragma unroll
        for (int ks = 0; ks < 8; ks++) {
            const int kb = ks * 32;
            uint32_t a[2][4];
            LDSM4(a[0][0], a[0][1], a[0][2], a[0][3], ab + aoff0 + kb);
            LDSM4(a[1][0], a[1][1], a[1][2], a[1][3], ab + aoff1 + kb);
#pragma unroll
            for (int p = 0; p < 4; p++) {
                uint32_t b0, b1, b2, b3;
                LDSM4(b0, b1, b2, b3, bb + boff[p] + kb);
                mma16(acc[0][2 * p],     a[0][0], a[0][1], a[0][2], a[0][3], b0, b1);
                mma16(acc[1][2 * p],     a[1][0], a[1][1], a[1][2], a[1][3], b0, b1);
                mma16(acc[0][2 * p + 1], a[0][0], a[0][1], a[0][2], a[0][3], b2, b3);
                mma16(acc[1][2 * p + 1], a[1][0], a[1][1], a[1][2], a[1][3], b2, b3);
            }
        }

#pragma unroll
        for (int mt = 0; mt < 2; mt++) {
            int row = m0 + mw * 32 + mt * 16 + r;
#pragma unroll
            for (int j = 0; j < 8; j++) {
                int col = nb + nw * 64 + j * 8 + 2 * cc;
                *reinterpret_cast<float2*>(&out[(size_t)row * Oo + col]) =
                    make_float2(acc[mt][j][0], acc[mt][j][1]);
                *reinterpret_cast<float2*>(&out[(size_t)(row + 8) * Oo + col]) =
                    make_float2(acc[mt][j][2], acc[mt][j][3]);
            }
        }
        if (nextsame) buf ^= 1;
    }
}

// ---------------------------------------------------------------------------
extern "C" void kernel_launch(void* const* d_in, const int* in_sizes, int n_in,
                              void* d_out, int out_size) {
    const float* x  = (const float*)d_in[0];
    const float* A  = (const float*)d_in[1];
    const float* Bm = (const float*)d_in[2];
    const float* Wr = (const float*)d_in[3];
    const float* br = (const float*)d_in[4];
    float* out = (float*)d_out;

    cudaFuncSetAttribute(k1_low, cudaFuncAttributeMaxDynamicSharedMemorySize, K1_SMEM);
    cudaFuncSetAttribute(k1_epi, cudaFuncAttributeMaxDynamicSharedMemorySize, 73728);
    cudaFuncSetAttribute(k2_up,  cudaFuncAttributeMaxDynamicSharedMemorySize, K2_SMEM);

    prep<<<136 * Dk / 4 / 256, 256>>>(A, Wr, Bm);
    k1_low<<<64 * KSPL, 256, K1_SMEM>>>(x);
    k1_epi<<<NTOK / 128, 256, 73728>>>(br);
    k2_up<<<GRID2, 256, K2_SMEM>>>(out);
}